// round 1
// baseline (speedup 1.0000x reference)
#include <cuda_runtime.h>
#include <cuda_bf16.h>

#define NUM_CLASSES 1000
#define FEAT_DIM    512
#define BATCH       65536

// scratch (no allocations allowed)
__device__ int   g_counts[NUM_CLASSES];
__device__ float g_inv[NUM_CLASSES];

__global__ void zero_kernel(float* out) {
    int i = blockIdx.x * blockDim.x + threadIdx.x;
    if (i < NUM_CLASSES) g_counts[i] = 0;
    if (i == 0) out[0] = 0.0f;
}

__global__ void count_kernel(const long long* __restrict__ labels) {
    int i = blockIdx.x * blockDim.x + threadIdx.x;
    if (i < BATCH) atomicAdd(&g_counts[(int)labels[i]], 1);
}

__global__ void inv_kernel() {
    int j = blockIdx.x * blockDim.x + threadIdx.x;
    if (j < NUM_CLASSES) {
        int c = g_counts[j];
        g_inv[j] = (c > 0) ? 1.0f / ((float)c * (float)FEAT_DIM * (float)BATCH) : 0.0f;
    }
}

// one warp per sample; 8 warps per block
__global__ __launch_bounds__(256) void dist_kernel(
    const float4* __restrict__ feat,
    const float4* __restrict__ cent,
    const long long* __restrict__ labels,
    float* __restrict__ out)
{
    const int tid    = blockIdx.x * blockDim.x + threadIdx.x;
    const int sample = tid >> 5;
    const int lane   = threadIdx.x & 31;
    const int wid    = threadIdx.x >> 5;

    const int lbl = (int)labels[sample];   // broadcast load (all lanes same addr)

    const float4* fr = feat + (size_t)sample * (FEAT_DIM / 4);
    const float4* cr = cent + (size_t)lbl    * (FEAT_DIM / 4);

    float acc = 0.0f;
#pragma unroll
    for (int k = 0; k < 4; k++) {
        float4 a = fr[lane + 32 * k];
        float4 b = cr[lane + 32 * k];
        float dx = a.x - b.x;
        float dy = a.y - b.y;
        float dz = a.z - b.z;
        float dw = a.w - b.w;
        acc = fmaf(dx, dx, acc);
        acc = fmaf(dy, dy, acc);
        acc = fmaf(dz, dz, acc);
        acc = fmaf(dw, dw, acc);
    }

    // warp reduce
#pragma unroll
    for (int off = 16; off > 0; off >>= 1)
        acc += __shfl_xor_sync(0xFFFFFFFFu, acc, off);

    __shared__ float s[8];
    if (lane == 0) s[wid] = acc * g_inv[lbl];
    __syncthreads();

    if (threadIdx.x == 0) {
        float t = 0.0f;
#pragma unroll
        for (int w = 0; w < 8; w++) t += s[w];
        atomicAdd(out, t);
    }
}

extern "C" void kernel_launch(void* const* d_in, const int* in_sizes, int n_in,
                              void* d_out, int out_size) {
    const float4*    feat   = (const float4*)d_in[0];
    const float4*    cent   = (const float4*)d_in[1];
    const long long* labels = (const long long*)d_in[2];
    float* out = (float*)d_out;

    zero_kernel<<<(NUM_CLASSES + 255) / 256, 256>>>(out);
    count_kernel<<<(BATCH + 255) / 256, 256>>>(labels);
    inv_kernel<<<(NUM_CLASSES + 255) / 256, 256>>>();
    // 8 warps (samples) per block -> 65536/8 = 8192 blocks
    dist_kernel<<<BATCH / 8, 256>>>(feat, cent, labels, out);
}